// round 1
// baseline (speedup 1.0000x reference)
#include <cuda_runtime.h>
#include <cuda_bf16.h>
#include <stdint.h>

// ---------------------------------------------------------------------------
// QLoRA linear:  out[M, Dout] = x[M, Din] @ (dequant_nf4(codes, scales)
//                                            + SCALING * lora_B @ lora_A)^T
// M = B*S = 8192, Din = Dout = 4096, R = 16, SCALING = 2.0
//
// Strategy (round 0 baseline):
//   kernel 1: build W_eff[o, i] = NF4[code]*scale + 2.0 * sum_r B[o,r]*A[r,i]
//             into a __device__ global fp32 buffer (rank-16 fold -> 1 GEMM).
//   kernel 2: fp32 SIMT tiled GEMM (both operands K-major), 128x128x16 tiles,
//             256 threads, 8x8 per-thread micro tile, float4 IO.
// ---------------------------------------------------------------------------

#define D_INF   4096
#define D_OUTF  4096
#define RANK    16
#define NF4_BLK 64
#define NBLKS   (D_INF / NF4_BLK)   // 64
#define LORA_SCALING 2.0f

__constant__ float c_nf4[16] = {
    -1.0f, -0.6961928009986877f, -0.5250730514526367f, -0.39491748809814453f,
    -0.28444138169288635f, -0.18477343022823334f, -0.09105003625154495f, 0.0f,
    0.07958029955625534f, 0.16093020141124725f, 0.24611230194568634f,
    0.33791524171829224f, 0.44070982933044434f, 0.5626170039176941f, 1.0f
};
// note: index 14 must be 0.7229568362236023f, index 15 = 1.0f — fixed below
// (kept as a full correct table; see c_nf4_full)
__constant__ float c_nf4_full[16] = {
    -1.0f,
    -0.6961928009986877f,
    -0.5250730514526367f,
    -0.39491748809814453f,
    -0.28444138169288635f,
    -0.18477343022823334f,
    -0.09105003625154495f,
     0.0f,
     0.07958029955625534f,
     0.16093020141124725f,
     0.24611230194568634f,
     0.33791524171829224f,
     0.44070982933044434f,
     0.5626170039176941f,
     0.7229568362236023f,
     1.0f
};

// Effective weight (dequant + folded LoRA), fp32: 4096*4096*4 = 64 MiB.
__device__ float g_Weff[(size_t)D_OUTF * D_INF];

// ---------------------------------------------------------------------------
// Kernel 1: build W_eff.
// One thread per element (o, i). Warp covers 32 consecutive i of the same o:
//   codes read coalesced, scale broadcast, lora_B[o, r] uniform,
//   lora_A[r, i] coalesced (A is 256 KB -> L2 resident).
// ---------------------------------------------------------------------------
__global__ void build_weff_kernel(const int*   __restrict__ codes,
                                  const float* __restrict__ scales,
                                  const float* __restrict__ lora_A,
                                  const float* __restrict__ lora_B)
{
    const int idx = blockIdx.x * blockDim.x + threadIdx.x;   // < 2^24, fits int
    const int i = idx & (D_INF - 1);
    const int o = idx >> 12;                                  // idx / 4096

    const int   c = codes[idx] & 15;
    const float s = scales[o * NBLKS + (i >> 6)];

    float l = 0.0f;
#pragma unroll
    for (int r = 0; r < RANK; r++) {
        l = fmaf(lora_A[r * D_INF + i], lora_B[o * RANK + r], l);
    }

    g_Weff[idx] = fmaf(c_nf4_full[c], s, LORA_SCALING * l);
}

// ---------------------------------------------------------------------------
// Kernel 2: fp32 SIMT GEMM, C[M, N] = A[M, K] * B[N, K]^T
//   A = x (K-major), B = g_Weff (K-major). M=8192, N=4096, K=4096.
//   BM=BN=128, BK=16, 256 threads, TM=TN=8.
// ---------------------------------------------------------------------------
#define BM 128
#define BN 128
#define BK 16
#define TM 8
#define TN 8

__global__ __launch_bounds__(256, 2)
void sgemm_nt_kernel(const float* __restrict__ A,
                     float*       __restrict__ C,
                     int M)
{
    __shared__ float As[BK][BM];
    __shared__ float Bs[BK][BN];

    const int tid = threadIdx.x;
    const int bx  = blockIdx.x;   // N tile index
    const int by  = blockIdx.y;   // M tile index

    const float* Ablk = A      + (size_t)by * BM * D_INF;
    const float* Bblk = g_Weff + (size_t)bx * BN * D_INF;

    // Tile loaders: 4 threads per row (BK=16 -> 4 floats per thread, 1x float4),
    // 256 threads cover 64 rows per pass -> 2 passes for 128 rows.
    const int lrow = tid >> 2;          // 0..63
    const int lcol = (tid & 3) << 2;    // 0,4,8,12

    // Compute layout: 16x16 thread grid, each thread owns an 8x8 C micro-tile.
    const int tx = tid & 15;
    const int ty = tid >> 4;

    float acc[TM][TN];
#pragma unroll
    for (int m = 0; m < TM; m++)
#pragma unroll
        for (int n = 0; n < TN; n++) acc[m][n] = 0.0f;

    float regM[TM], regN[TN];

    for (int k0 = 0; k0 < D_INF; k0 += BK) {
#pragma unroll
        for (int rr = 0; rr < 2; rr++) {
            const int row = lrow + rr * 64;
            const float4 va = *(const float4*)(Ablk + (size_t)row * D_INF + k0 + lcol);
            As[lcol + 0][row] = va.x;
            As[lcol + 1][row] = va.y;
            As[lcol + 2][row] = va.z;
            As[lcol + 3][row] = va.w;
            const float4 vb = *(const float4*)(Bblk + (size_t)row * D_INF + k0 + lcol);
            Bs[lcol + 0][row] = vb.x;
            Bs[lcol + 1][row] = vb.y;
            Bs[lcol + 2][row] = vb.z;
            Bs[lcol + 3][row] = vb.w;
        }
        __syncthreads();

#pragma unroll
        for (int k = 0; k < BK; k++) {
#pragma unroll
            for (int m = 0; m < TM; m++) regM[m] = As[k][ty * TM + m];
#pragma unroll
            for (int n = 0; n < TN; n++) regN[n] = Bs[k][tx * TN + n];
#pragma unroll
            for (int m = 0; m < TM; m++)
#pragma unroll
                for (int n = 0; n < TN; n++)
                    acc[m][n] = fmaf(regM[m], regN[n], acc[m][n]);
        }
        __syncthreads();
    }

    // Epilogue: vectorized stores.
#pragma unroll
    for (int m = 0; m < TM; m++) {
        float* Crow = C + (size_t)(by * BM + ty * TM + m) * D_OUTF + bx * BN + tx * TN;
#pragma unroll
        for (int n = 0; n < TN; n += 4) {
            float4 v = make_float4(acc[m][n], acc[m][n + 1], acc[m][n + 2], acc[m][n + 3]);
            *(float4*)(Crow + n) = v;
        }
    }
    (void)M;
}

// ---------------------------------------------------------------------------
// kernel_launch — graph-capturable, allocation-free.
// Inputs (metadata order): x[f32], codes[i32], scales[f32], lora_A[f32], lora_B[f32]
// Output: f32 [B, S, Dout] = [M, Dout]
// ---------------------------------------------------------------------------
extern "C" void kernel_launch(void* const* d_in, const int* in_sizes, int n_in,
                              void* d_out, int out_size)
{
    const float* x      = (const float*)d_in[0];
    const int*   codes  = (const int*)  d_in[1];
    const float* scales = (const float*)d_in[2];
    const float* lora_A = (const float*)d_in[3];
    const float* lora_B = (const float*)d_in[4];
    float*       out    = (float*)d_out;

    const int M = in_sizes[0] / D_INF;   // 8192

    // 1) Build effective weight (dequant + folded rank-16 LoRA).
    {
        const int total   = D_OUTF * D_INF;          // 16,777,216
        const int threads = 256;
        const int blocks  = total / threads;
        build_weff_kernel<<<blocks, threads>>>(codes, scales, lora_A, lora_B);
    }

    // 2) Single big GEMM: out = x @ W_eff^T
    {
        dim3 grid(D_OUTF / BN, M / BM);  // (32, 64)
        sgemm_nt_kernel<<<grid, 256>>>(x, out, M);
    }

    (void)n_in; (void)out_size;
}

// round 9
// speedup vs baseline: 11.5344x; 11.5344x over previous
#include <cuda_runtime.h>
#include <cuda_fp16.h>
#include <stdint.h>

// ---------------------------------------------------------------------------
// QLoRA linear on sm_103 (portable-PTX tensor path: mma.sync HMMA).
//   out[M, 4096] = x[M, 4096] @ (dequant_nf4(codes, scales) + 2.0 * B@A)^T
//
//   Prologue 1: W_eff fp16 [4096, 4096]  (dequant + folded rank-16 LoRA)
//   Prologue 2: x fp16 [M, 4096]
//   Main: fp16 HMMA GEMM, fp32 accum, C = Xh @ Wh^T (both K-major -> NT)
//         BM=BN=128, BK=32, 2-stage cp.async double buffer, static 40KB smem.
//
//   FIX vs previous round: g_Xh/g_Wh are referenced from DEVICE code inside
//   the GEMM kernel. Previously they were passed as host-side kernel args,
//   which passes the host shadow address (readable via ATS on GB300!) and
//   silently yields all-zero operands.
// ---------------------------------------------------------------------------

#define D_INF   4096
#define D_OUTF  4096
#define RANK    16
#define LORA_SCALING 2.0f
#define MAX_M   8192

#define BM 128
#define BN 128
#define BK 32
#define NIT (D_INF / BK)            // 128

// smem tile row: 32 halfs = 64B data + 16B pad = 80B stride.
// ldmatrix 8-row phase banks: r*20 mod 32 -> {0,20,8,28,16,4,24,12} conflict-free.
#define ROW_B 80

__constant__ float c_nf4[16] = {
    -1.0f, -0.6961928009986877f, -0.5250730514526367f, -0.39491748809814453f,
    -0.28444138169288635f, -0.18477343022823334f, -0.09105003625154495f, 0.0f,
    0.07958029955625534f, 0.16093020141124725f, 0.24611230194568634f,
    0.33791524171829224f, 0.44070982933044434f, 0.5626170039176941f,
    0.7229568362236023f, 1.0f
};

__device__ __align__(128) __half g_Xh[(size_t)MAX_M * D_INF];    // 64 MiB
__device__ __align__(128) __half g_Wh[(size_t)D_OUTF * D_INF];   // 32 MiB

// ------------------------------ PTX helpers -------------------------------
__device__ __forceinline__ uint32_t smem_u32(const void* p) {
    uint32_t a;
    asm("{ .reg .u64 t; cvta.to.shared.u64 t, %1; cvt.u32.u64 %0, t; }"
        : "=r"(a) : "l"(p));
    return a;
}

__device__ __forceinline__ void cp_async16(uint32_t dst, const void* src) {
    asm volatile("cp.async.cg.shared.global [%0], [%1], 16;"
                 :: "r"(dst), "l"(src) : "memory");
}
#define CP_COMMIT() asm volatile("cp.async.commit_group;" ::: "memory")
#define CP_WAIT1()  asm volatile("cp.async.wait_group 1;" ::: "memory")

#define LDSM_X4(r, addr) \
    asm volatile("ldmatrix.sync.aligned.m8n8.x4.shared.b16 {%0,%1,%2,%3}, [%4];" \
                 : "=r"((r)[0]), "=r"((r)[1]), "=r"((r)[2]), "=r"((r)[3]) \
                 : "r"(addr))

__device__ __forceinline__ void mma16816(float* c, const uint32_t* a,
                                         uint32_t b0, uint32_t b1) {
    asm volatile(
        "mma.sync.aligned.m16n8k16.row.col.f32.f16.f16.f32 "
        "{%0,%1,%2,%3}, {%4,%5,%6,%7}, {%8,%9}, {%0,%1,%2,%3};"
        : "+f"(c[0]), "+f"(c[1]), "+f"(c[2]), "+f"(c[3])
        : "r"(a[0]), "r"(a[1]), "r"(a[2]), "r"(a[3]), "r"(b0), "r"(b1));
}

// ---------------------------------------------------------------------------
// Prologue 1: W_eff fp16 = nf4[code]*scale + 2.0 * (lora_B @ lora_A)
// One thread per 2 consecutive input-dim elements.
// ---------------------------------------------------------------------------
__global__ void build_wh_kernel(const int*   __restrict__ codes,
                                const float* __restrict__ scales,
                                const float* __restrict__ lora_A,
                                const float* __restrict__ lora_B)
{
    const int gid = blockIdx.x * blockDim.x + threadIdx.x;   // < 8,388,608
    const int p = gid & 2047;          // half2 index within the row
    const int o = gid >> 11;           // output feature

    const int2 cc = ((const int2*)codes)[gid];
    const float s = scales[o * (D_INF / 64) + (p >> 5)];

    float l0 = 0.0f, l1 = 0.0f;
#pragma unroll
    for (int r = 0; r < RANK; r++) {
        const float2 a2 = ((const float2*)(lora_A + r * D_INF))[p];
        const float  b  = lora_B[o * RANK + r];
        l0 = fmaf(a2.x, b, l0);
        l1 = fmaf(a2.y, b, l1);
    }

    const float w0 = fmaf(c_nf4[cc.x & 15], s, LORA_SCALING * l0);
    const float w1 = fmaf(c_nf4[cc.y & 15], s, LORA_SCALING * l1);

    ((__half2*)(g_Wh + (size_t)o * D_INF))[p] = __floats2half2_rn(w0, w1);
}

// ---------------------------------------------------------------------------
// Prologue 2: x -> fp16
// ---------------------------------------------------------------------------
__global__ void build_xh_kernel(const float* __restrict__ x)
{
    const int gid = blockIdx.x * blockDim.x + threadIdx.x;   // < M*2048
    const float2 v = ((const float2*)x)[gid];
    ((__half2*)g_Xh)[gid] = __floats2half2_rn(v.x, v.y);
}

// ---------------------------------------------------------------------------
// Main GEMM: C[M, 4096] = g_Xh[M, 4096] @ g_Wh[4096, 4096]^T, fp32 accum.
// 256 threads = 8 warps, warp grid 2(M) x 4(N), warptile 64x32.
// Static smem, 2-stage double buffer. Operands read via device globals.
// ---------------------------------------------------------------------------
__global__ __launch_bounds__(256, 2)
void hgemm_nt_kernel(float* __restrict__ C)
{
    __shared__ __align__(128) uint8_t sAbuf[2][BM * ROW_B];   // 2 x 10240
    __shared__ __align__(128) uint8_t sBbuf[2][BN * ROW_B];   // 2 x 10240

    const int tid  = threadIdx.x;
    const int lane = tid & 31;
    const int wid  = tid >> 5;
    const int wm   = wid >> 2;        // 0..1  (M half of CTA tile)
    const int wn   = wid & 3;         // 0..3  (N quarter)
    const int bn   = blockIdx.x;
    const int bm   = blockIdx.y;

    // --- global->smem geometry: 4 threads/row (16B each), 64 rows/pass ---
    const int lrow = tid >> 2;                 // 0..63
    const int lchk = (tid & 3) << 4;           // 0,16,32,48 bytes
    const __half* Ag = g_Xh + (size_t)(bm * BM + lrow) * D_INF + (tid & 3) * 8;
    const __half* Bg = g_Wh + (size_t)(bn * BN + lrow) * D_INF + (tid & 3) * 8;

    const uint32_t sA0 = smem_u32(&sAbuf[0][0]);
    const uint32_t sB0 = smem_u32(&sBbuf[0][0]);
    const uint32_t dA  = sA0 + lrow * ROW_B + lchk;
    const uint32_t dB  = sB0 + lrow * ROW_B + lchk;

    // --- ldmatrix per-lane byte offsets within a tile ---
    const int lr = lane & 7;
    const uint32_t aoff = (uint32_t)((lr + ((lane >> 3) & 1) * 8) * ROW_B + (lane >> 4) * 16);
    const uint32_t boff = (uint32_t)((lr + (lane >> 4) * 8) * ROW_B + ((lane >> 3) & 1) * 16);

    float acc[4][4][4];
#pragma unroll
    for (int m = 0; m < 4; m++)
#pragma unroll
        for (int n = 0; n < 4; n++)
#pragma unroll
            for (int t = 0; t < 4; t++) acc[m][n][t] = 0.0f;

    // --- prologue: load stage 0 into slot 0 ---
    {
        cp_async16(dA,                         Ag);
        cp_async16(dA + 64 * ROW_B,            Ag + (size_t)64 * D_INF);
        cp_async16(dB,                         Bg);
        cp_async16(dB + 64 * ROW_B,            Bg + (size_t)64 * D_INF);
        CP_COMMIT();
    }

    for (int i = 0; i < NIT; i++) {
        // issue next stage load into the other slot (empty group on last iter)
        if (i + 1 < NIT) {
            const uint32_t so = (uint32_t)((i + 1) & 1) * (uint32_t)(BM * ROW_B);
            const size_t k0 = (size_t)(i + 1) * BK;
            cp_async16(dA + so,                Ag + k0);
            cp_async16(dA + so + 64 * ROW_B,   Ag + (size_t)64 * D_INF + k0);
            cp_async16(dB + so,                Bg + k0);
            cp_async16(dB + so + 64 * ROW_B,   Bg + (size_t)64 * D_INF + k0);
        }
        CP_COMMIT();
        CP_WAIT1();               // stage i resident (this thread)
        __syncthreads();          // resident block-wide

        // compute stage i
        const uint32_t so = (uint32_t)(i & 1) * (uint32_t)(BM * ROW_B);
        const uint32_t ab = sA0 + so + (uint32_t)(wm * 64) * ROW_B + aoff;
        const uint32_t bb = sB0 + so + (uint32_t)(wn * 32) * ROW_B + boff;

#pragma unroll
        for (int kf = 0; kf < 2; kf++) {
            uint32_t af[4][4], bf[2][4];
#pragma unroll
            for (int mf = 0; mf < 4; mf++)
                LDSM_X4(af[mf], ab + (uint32_t)(mf * 16) * ROW_B + kf * 32);
#pragma unroll
            for (int nf2 = 0; nf2 < 2; nf2++)
                LDSM_X4(bf[nf2], bb + (uint32_t)(nf2 * 16) * ROW_B + kf * 32);
#pragma unroll
            for (int mf = 0; mf < 4; mf++)
#pragma unroll
                for (int nf = 0; nf < 4; nf++)
                    mma16816(acc[mf][nf], af[mf],
                             bf[nf >> 1][(nf & 1) * 2], bf[nf >> 1][(nf & 1) * 2 + 1]);
        }
        __syncthreads();          // protect slot i&1 before it is overwritten
    }

    // --- epilogue: c0,c1 -> (row, col); c2,c3 -> (row+8, col) ---
#pragma unroll
    for (int mf = 0; mf < 4; mf++) {
        const int row = bm * BM + wm * 64 + mf * 16 + (lane >> 2);
        float* r0 = C + (size_t)row * D_OUTF + bn * BN + wn * 32 + (lane & 3) * 2;
        float* r1 = r0 + (size_t)8 * D_OUTF;
#pragma unroll
        for (int nf = 0; nf < 4; nf++) {
            *(float2*)(r0 + nf * 8) = make_float2(acc[mf][nf][0], acc[mf][nf][1]);
            *(float2*)(r1 + nf * 8) = make_float2(acc[mf][nf][2], acc[mf][nf][3]);
        }
    }
}

// ---------------------------------------------------------------------------
// kernel_launch — graph-capturable, allocation-free, attribute-free.
// Inputs: x[f32], codes[i32], scales[f32], lora_A[f32], lora_B[f32]; out f32.
// ---------------------------------------------------------------------------
extern "C" void kernel_launch(void* const* d_in, const int* in_sizes, int n_in,
                              void* d_out, int out_size)
{
    const float* x      = (const float*)d_in[0];
    const int*   codes  = (const int*)  d_in[1];
    const float* scales = (const float*)d_in[2];
    const float* lora_A = (const float*)d_in[3];
    const float* lora_B = (const float*)d_in[4];
    float*       out    = (float*)d_out;

    const int M = in_sizes[0] / D_INF;   // 8192

    build_wh_kernel<<<(D_OUTF * 2048) / 256, 256>>>(codes, scales, lora_A, lora_B);
    build_xh_kernel<<<(M * 2048) / 256, 256>>>(x);

    dim3 grid(D_OUTF / BN, M / BM);   // (32, 64)
    hgemm_nt_kernel<<<grid, 256>>>(out);

    (void)n_in; (void)out_size;
}